// round 3
// baseline (speedup 1.0000x reference)
#include <cuda_runtime.h>

#define THREADS 256
#define NBATCH  4

// ---------- packed f32x2 helpers (sm_100+ PTX) ----------
__device__ __forceinline__ unsigned long long pk2(float lo, float hi) {
    unsigned long long r;
    asm("mov.b64 %0, {%1, %2};" : "=l"(r) : "f"(lo), "f"(hi));
    return r;
}
__device__ __forceinline__ void upk2(unsigned long long v, float& lo, float& hi) {
    asm("mov.b64 {%0, %1}, %2;" : "=f"(lo), "=f"(hi) : "l"(v));
}
__device__ __forceinline__ void ffma2(unsigned long long& acc, unsigned long long a, unsigned long long b) {
    asm("fma.rn.f32x2 %0, %1, %2, %0;" : "+l"(acc) : "l"(a), "l"(b));
}
__device__ __forceinline__ float rsqrt_approx(float x) {
    float r;
    asm("rsqrt.approx.f32 %0, %1;" : "=f"(r) : "f"(x));
    return r;
}

// smem layout (floats):
//  W_sh   [256][16]       4096
//  b_sh   [16]            16
//  ed_sh  [8][16][3][3]   1152
//  ei_sh  [8][16]         128
//  xs     [64][260]       16640   (stride 260: conflict-free LDS.128 across rows)
//  rssh   [64][25]        1600    (stride 25: conflict-free)
//  aug    [4][16][18]     1152    (M^T augmented with e0; stride 18)
//  col0   [4][16]         64
#define SMEM_FLOATS (4096 + 16 + 1152 + 128 + 64*260 + 64*25 + 4*16*18 + 64)

__global__ __launch_bounds__(THREADS, 2)
void ocae_kernel(const float* __restrict__ eq, const float* __restrict__ rei,
                 const float* __restrict__ W,  const float* __restrict__ bias,
                 const float* __restrict__ envdim, const float* __restrict__ envion,
                 float* __restrict__ out)
{
    extern __shared__ float sm[];
    float* W_sh  = sm;                 // 4096
    float* b_sh  = W_sh + 4096;        // 16
    float* ed_sh = b_sh + 16;          // 1152
    float* ei_sh = ed_sh + 1152;       // 128
    float* xs    = ei_sh + 128;        // 64*260
    float* rssh  = xs + 64*260;        // 64*25
    float* aug   = rssh + 64*25;       // 4*16*18
    float* col0  = aug + 4*16*18;      // 64

    const int tid = threadIdx.x;
    const int s   = blockIdx.x & 1;
    const int b0  = (blockIdx.x >> 1) * NBATCH;

    // ---------------- stage constants & inputs ----------------
    for (int i = tid; i < 4096; i += THREADS) W_sh[i]  = W[s*4096 + i];
    for (int i = tid; i < 1152; i += THREADS) ed_sh[i] = envdim[s*1152 + i];
    if (tid < 128) ei_sh[tid] = envion[s*128 + tid];
    if (tid < 16)  b_sh[tid]  = bias[s*16 + tid];

    // xs: 64 local rows (4 b x 16 n), 256 floats each, float4 coalesced
    for (int i = tid; i < 64*64; i += THREADS) {
        int r  = i >> 6;
        int c4 = i & 63;
        int grow = (b0 + (r >> 4)) * 32 + s*16 + (r & 15);
        float4 v = *reinterpret_cast<const float4*>(eq + (size_t)grow*256 + c4*4);
        *reinterpret_cast<float4*>(xs + r*260 + c4*4) = v;
    }
    // rs: 64 rows x 24 floats
    for (int i = tid; i < 64*24; i += THREADS) {
        int r = i / 24;
        int c = i - r*24;
        int grow = (b0 + (r >> 4)) * 32 + s*16 + (r & 15);
        rssh[r*25 + c] = rei[(size_t)grow*24 + c];
    }
    __syncthreads();

    // ---------------- GEMM: y[row][o] for o = ob..ob+3 ----------------
    const int row = tid >> 2;   // 0..63  (matrix = row>>4, n = row&15)
    const int og  = tid & 3;
    const int ob  = og * 4;

    unsigned long long acc01 = pk2(b_sh[ob+0], b_sh[ob+1]);
    unsigned long long acc23 = pk2(b_sh[ob+2], b_sh[ob+3]);
    const float* xrow = xs + row*260;

    #pragma unroll 4
    for (int dq = 0; dq < 64; dq++) {
        float4 x4 = *reinterpret_cast<const float4*>(xrow + dq*4);
        const float* wb = W_sh + dq*64 + ob;   // (dq*4)*16 + ob
        {
            ulonglong2 w = *reinterpret_cast<const ulonglong2*>(wb);
            unsigned long long xx = pk2(x4.x, x4.x);
            ffma2(acc01, xx, w.x); ffma2(acc23, xx, w.y);
        }
        {
            ulonglong2 w = *reinterpret_cast<const ulonglong2*>(wb + 16);
            unsigned long long xx = pk2(x4.y, x4.y);
            ffma2(acc01, xx, w.x); ffma2(acc23, xx, w.y);
        }
        {
            ulonglong2 w = *reinterpret_cast<const ulonglong2*>(wb + 32);
            unsigned long long xx = pk2(x4.z, x4.z);
            ffma2(acc01, xx, w.x); ffma2(acc23, xx, w.y);
        }
        {
            ulonglong2 w = *reinterpret_cast<const ulonglong2*>(wb + 48);
            unsigned long long xx = pk2(x4.w, x4.w);
            ffma2(acc01, xx, w.x); ffma2(acc23, xx, w.y);
        }
    }
    float y[4];
    upk2(acc01, y[0], y[1]);
    upk2(acc23, y[2], y[3]);

    // ---------------- env: sum_i exp(-||A_{io} r_i||) * env_ion[i][o] ----------------
    float env[4] = {0.f, 0.f, 0.f, 0.f};
    const float* rr = rssh + row*25;
    for (int i = 0; i < 8; i++) {
        float r0 = rr[i*3+0], r1 = rr[i*3+1], r2 = rr[i*3+2];
        const float* A  = ed_sh + (i*16 + ob)*9;
        const float* ei = ei_sh + i*16 + ob;
        #pragma unroll
        for (int j = 0; j < 4; j++) {
            const float* Aj = A + j*9;
            float a0 = Aj[0]*r0 + Aj[1]*r1 + Aj[2]*r2;
            float a1 = Aj[3]*r0 + Aj[4]*r1 + Aj[5]*r2;
            float a2 = Aj[6]*r0 + Aj[7]*r1 + Aj[8]*r2;
            float t  = a0*a0 + a1*a1 + a2*a2;
            float nrm = t * rsqrt_approx(fmaxf(t, 1e-35f));  // sqrt(t), safe at 0
            env[j] += __expf(-nrm) * ei[j];
        }
    }

    // ---------------- M = y*env; write M^T (augmented) ----------------
    const int mtx = row >> 4;
    const int n   = row & 15;
    float* am = aug + mtx*288;   // [16][18]
    #pragma unroll
    for (int j = 0; j < 4; j++) {
        float m = y[j] * env[j];
        am[(ob + j)*18 + n] = m;               // aug[o][n] = M[n][o] = (M^T)[o][n]
        if (ob + j == 0 ) col0[mtx*16 + n] = m;
        if (n == 0) am[(ob + j)*18 + 16] = (ob + j == 0) ? 1.f : 0.f;  // rhs e0
    }
    __syncthreads();

    // ---------------- cofactors via LU of M^T (one warp per matrix) ----------------
    const int wid  = tid >> 5;
    const int lane = tid & 31;
    if (wid < 4) {
        float* a = aug + wid*288;
        const unsigned FULL = 0xffffffffu;
        float sign = 1.f;

        for (int k = 0; k < 15; k++) {
            // partial pivot on column k (rows k..15)
            float v = (lane >= k && lane < 16) ? fabsf(a[lane*18 + k]) : -1.f;
            int p = lane;
            #pragma unroll
            for (int off = 16; off; off >>= 1) {
                float ov = __shfl_xor_sync(FULL, v, off);
                int   op = __shfl_xor_sync(FULL, p, off);
                if (ov > v || (ov == v && op < p)) { v = ov; p = op; }
            }
            if (p != k) {
                if (lane <= 16) {
                    float t0 = a[k*18 + lane];
                    a[k*18 + lane] = a[p*18 + lane];
                    a[p*18 + lane] = t0;
                }
                sign = -sign;
            }
            __syncwarp(FULL);
            float piv = a[k*18 + k];
            if (lane > k && lane < 16) {
                float mlt = a[lane*18 + k] / piv;
                for (int j = k + 1; j <= 16; j++)
                    a[lane*18 + j] -= mlt * a[k*18 + j];
            }
            __syncwarp(FULL);
        }

        // det(M) = sign * prod(diag)
        float diag = (lane < 16) ? a[lane*18 + lane] : 1.f;
        float det = diag;
        #pragma unroll
        for (int off = 16; off; off >>= 1) det *= __shfl_xor_sync(FULL, det, off);
        det *= sign;

        // back-substitute U x = (L^-1 P e0), column sweep
        float yi = (lane < 16) ? a[lane*18 + 16] : 0.f;
        float xv = 0.f;
        for (int k = 15; k >= 0; k--) {
            float xk = __shfl_sync(FULL, yi, k) / __shfl_sync(FULL, diag, k);
            if (lane == k) xv = xk;
            if (lane < k)  yi -= a[lane*18 + k] * xk;
        }

        // cof_i = M[i,0] * det * (M^-T e0)_i
        if (lane < 16) {
            int b = b0 + wid;
            out[(b*2 + s)*16 + lane] = col0[wid*16 + lane] * det * xv;
        }
    }
}

extern "C" void kernel_launch(void* const* d_in, const int* in_sizes, int n_in,
                              void* d_out, int out_size)
{
    const float* eq  = (const float*)d_in[0];
    const float* rei = (const float*)d_in[1];
    const float* W   = (const float*)d_in[2];
    const float* b   = (const float*)d_in[3];
    const float* ed  = (const float*)d_in[4];
    const float* ei  = (const float*)d_in[5];
    float* out = (float*)d_out;

    int B = in_sizes[0] / (32 * 256);   // 4096
    int smem_bytes = SMEM_FLOATS * (int)sizeof(float);

    cudaFuncSetAttribute(ocae_kernel, cudaFuncAttributeMaxDynamicSharedMemorySize, smem_bytes);

    dim3 grid((B / NBATCH) * 2);
    ocae_kernel<<<grid, THREADS, smem_bytes>>>(eq, rei, W, b, ed, ei, out);
}

// round 4
// speedup vs baseline: 2.6909x; 2.6909x over previous
#include <cuda_runtime.h>

#define THREADS 128

// ---------- packed f32x2 helpers ----------
__device__ __forceinline__ unsigned long long pk2(float lo, float hi) {
    unsigned long long r;
    asm("mov.b64 %0, {%1, %2};" : "=l"(r) : "f"(lo), "f"(hi));
    return r;
}
__device__ __forceinline__ void upk2(unsigned long long v, float& lo, float& hi) {
    asm("mov.b64 {%0, %1}, %2;" : "=f"(lo), "=f"(hi) : "l"(v));
}
__device__ __forceinline__ void ffma2(unsigned long long& acc, unsigned long long a, unsigned long long b) {
    asm("fma.rn.f32x2 %0, %1, %2, %0;" : "+l"(acc) : "l"(a), "l"(b));
}
__device__ __forceinline__ unsigned long long mul2(unsigned long long a, unsigned long long b) {
    unsigned long long r; asm("mul.rn.f32x2 %0, %1, %2;" : "=l"(r) : "l"(a), "l"(b)); return r;
}
__device__ __forceinline__ float sqrt_ap(float x){ float r; asm("sqrt.approx.f32 %0, %1;" : "=f"(r) : "f"(x)); return r; }
__device__ __forceinline__ float rcp_ap (float x){ float r; asm("rcp.approx.f32 %0, %1;"  : "=f"(r) : "f"(x)); return r; }

// smem (floats): Wsh[256*16]=4096 | Ssh[8*8*12]=768 | eish[128] | Msh[8][16*17]=2176
#define SM_W  0
#define SM_S  4096
#define SM_EI (4096 + 768)
#define SM_M  (4096 + 768 + 128)
#define SMEM_FLOATS (4096 + 768 + 128 + 8*272)

__global__ __launch_bounds__(THREADS, 6)
void ocae2(const float* __restrict__ eq,  const float* __restrict__ rei,
           const float* __restrict__ Wg,  const float* __restrict__ bias,
           const float* __restrict__ envdim, const float* __restrict__ envion,
           float* __restrict__ out)
{
    __shared__ float sm[SMEM_FLOATS];
    const int tid = threadIdx.x;
    const int s   = blockIdx.x & 1;          // spin
    const int b0  = (blockIdx.x >> 1) * 8;   // 8 batches per block, single spin

    // ---------------- stage W, env constants ----------------
    {
        const float4* Wsrc = (const float4*)(Wg + (size_t)s * 4096);
        #pragma unroll
        for (int i = tid; i < 1024; i += THREADS)
            *(float4*)(sm + SM_W + i*4) = __ldg(Wsrc + i);

        sm[SM_EI + tid] = envion[s*128 + tid];   // layout [i][o] kept as-is (o-pairs adjacent)

        // S = A^T A per (i,o), stored as o-pair-interleaved float2 sextets
        int ii = tid >> 4, oo = tid & 15;
        const float* A = envdim + s*1152 + ii*144 + oo*9;   // [e][d] row-major
        float a00=A[0],a01=A[1],a02=A[2], a10=A[3],a11=A[4],a12=A[5], a20=A[6],a21=A[7],a22=A[8];
        float s00 = a00*a00 + a10*a10 + a20*a20;
        float s11 = a01*a01 + a11*a11 + a21*a21;
        float s22 = a02*a02 + a12*a12 + a22*a22;
        float s01 = 2.f*(a00*a01 + a10*a11 + a20*a21);
        float s02 = 2.f*(a00*a02 + a10*a12 + a20*a22);
        float s12 = 2.f*(a01*a02 + a11*a12 + a21*a22);
        float* dst = sm + SM_S + (ii*8 + (oo>>1))*12 + (oo&1);
        dst[0]=s00; dst[2]=s11; dst[4]=s22; dst[6]=s01; dst[8]=s02; dst[10]=s12;
    }
    __syncthreads();

    // ---------------- GEMM: 2 rows x 8 orbitals per thread ----------------
    const int h  = tid & 1;        // orbital half: o in [8h, 8h+8)
    const int rb = tid >> 1;       // local row 0..63  (rows rb and rb+64)
    const size_t grow0 = ((size_t)(b0 + (rb>>4))*32 + s*16 + (rb&15));
    const float4* xp0 = (const float4*)(eq + grow0*256);
    const float4* xp1 = (const float4*)(eq + (grow0 + 128)*256);  // +4 batches
    const float*  wp  = sm + SM_W + h*8;

    unsigned long long a0[4], a1[4];
    {
        float4 bv0 = *(const float4*)(bias + s*16 + h*8);
        float4 bv1 = *(const float4*)(bias + s*16 + h*8 + 4);
        a0[0]=pk2(bv0.x,bv0.y); a0[1]=pk2(bv0.z,bv0.w);
        a0[2]=pk2(bv1.x,bv1.y); a0[3]=pk2(bv1.z,bv1.w);
        a1[0]=a0[0]; a1[1]=a0[1]; a1[2]=a0[2]; a1[3]=a0[3];
    }

    #pragma unroll 2
    for (int dq = 0; dq < 64; dq++) {
        float4 v0 = __ldg(xp0 + dq);
        float4 v1 = __ldg(xp1 + dq);
        float x0a[4], x1a[4];
        *(float4*)x0a = v0; *(float4*)x1a = v1;
        #pragma unroll
        for (int e = 0; e < 4; e++) {
            const float* wr = wp + (dq*4 + e)*16;
            ulonglong2 wA = *(const ulonglong2*)(wr);
            ulonglong2 wB = *(const ulonglong2*)(wr + 4);
            unsigned long long xx0 = pk2(x0a[e], x0a[e]);
            ffma2(a0[0], xx0, wA.x); ffma2(a0[1], xx0, wA.y);
            ffma2(a0[2], xx0, wB.x); ffma2(a0[3], xx0, wB.y);
            unsigned long long xx1 = pk2(x1a[e], x1a[e]);
            ffma2(a1[0], xx1, wA.x); ffma2(a1[1], xx1, wA.y);
            ffma2(a1[2], xx1, wB.x); ffma2(a1[3], xx1, wB.y);
        }
    }

    // ---------------- env + M for the two rows ----------------
    #pragma unroll
    for (int rr = 0; rr < 2; rr++) {
        const int r = rb + rr*64;
        const size_t grow = ((size_t)(b0 + (r>>4))*32 + s*16 + (r&15));
        float rv[24];
        {
            const float4* rp = (const float4*)(rei + grow*24);
            #pragma unroll
            for (int q = 0; q < 6; q++) *(float4*)(rv + q*4) = __ldg(rp + q);
        }
        unsigned long long ev[4] = {0ull,0ull,0ull,0ull};
        #pragma unroll
        for (int i = 0; i < 8; i++) {
            float r0 = rv[i*3], r1 = rv[i*3+1], r2 = rv[i*3+2];
            unsigned long long p00 = pk2(r0*r0, r0*r0);
            unsigned long long p11 = pk2(r1*r1, r1*r1);
            unsigned long long p22 = pk2(r2*r2, r2*r2);
            unsigned long long p01 = pk2(r0*r1, r0*r1);
            unsigned long long p02 = pk2(r0*r2, r0*r2);
            unsigned long long p12 = pk2(r1*r2, r1*r2);
            const float* Sb = sm + SM_S + (i*8 + h*4)*12;
            const unsigned long long* Eb = (const unsigned long long*)(sm + SM_EI) + (i*8 + h*4);
            #pragma unroll
            for (int op = 0; op < 4; op++) {
                const ulonglong2* Sp = (const ulonglong2*)(Sb + op*12);
                ulonglong2 sA = Sp[0], sB = Sp[1], sC = Sp[2];
                unsigned long long q = 0ull;
                ffma2(q, sA.x, p00); ffma2(q, sA.y, p11); ffma2(q, sB.x, p22);
                ffma2(q, sB.y, p01); ffma2(q, sC.x, p02); ffma2(q, sC.y, p12);
                float q0, q1; upk2(q, q0, q1);
                float e0 = __expf(-sqrt_ap(fmaxf(q0, 0.f)));
                float e1 = __expf(-sqrt_ap(fmaxf(q1, 0.f)));
                ffma2(ev[op], pk2(e0, e1), Eb[op]);
            }
        }
        // M[n][o] = y * env  -> Msh[m][o][n]  (m = local matrix, n = row-in-matrix)
        unsigned long long* acc = rr ? a1 : a0;
        const int m = r >> 4;
        const int n = r & 15;
        float* Mb = sm + SM_M + m*272 + n;
        #pragma unroll
        for (int op = 0; op < 4; op++) {
            unsigned long long mm = mul2(acc[op], ev[op]);
            float m0, m1; upk2(mm, m0, m1);
            int o = h*8 + op*2;
            Mb[o*17] = m0; Mb[(o+1)*17] = m1;
        }
    }
    __syncwarp();   // warp w wrote matrices w and w+4; same warp reads them

    // ---------------- cofactors: register LU, 2 matrices per warp ----------------
    const unsigned FULL = 0xffffffffu;
    const int lane = tid & 31;
    const int w    = tid >> 5;
    const int seg  = lane >> 4;
    const int o    = lane & 15;          // row of A = M^T
    const int m    = w + seg*4;

    float a[17];
    {
        const float* Ma = sm + SM_M + m*272 + o*17;
        #pragma unroll
        for (int j = 0; j < 16; j++) a[j] = Ma[j];
        a[16] = (o == 0) ? 1.f : 0.f;    // rhs e0
    }
    float det = 1.f;

    #pragma unroll
    for (int k = 0; k < 16; k++) {
        // partial pivot over rows >= k (16-lane segment)
        float v = (o >= k) ? fabsf(a[k]) : -1.f;
        int   p = o;
        #pragma unroll
        for (int off = 8; off; off >>= 1) {
            float ov = __shfl_xor_sync(FULL, v, off, 16);
            int   oq = __shfl_xor_sync(FULL, p, off, 16);
            if (ov > v || (ov == v && oq < p)) { v = ov; p = oq; }
        }
        float pvk = __shfl_sync(FULL, a[k], p, 16);
        float kvk = __shfl_sync(FULL, a[k], k, 16);
        if (o == k) a[k] = pvk; else if (o == p) a[k] = kvk;
        det = (p != k) ? -det : det;
        det *= pvk;
        float mlt = (o > k) ? a[k] * rcp_ap(pvk) : 0.f;
        #pragma unroll
        for (int j = k + 1; j < 17; j++) {
            float pv = __shfl_sync(FULL, a[j], p, 16);
            float kv = __shfl_sync(FULL, a[j], k, 16);
            if (o == k) a[j] = pv; else if (o == p) a[j] = kv;
            a[j] -= mlt * pv;
        }
    }

    // back-substitution: U z = rhs
    float z = 0.f;
    float rhs = a[16];
    #pragma unroll
    for (int k = 15; k >= 0; k--) {
        float num = __shfl_sync(FULL, rhs,  k, 16);
        float den = __shfl_sync(FULL, a[k], k, 16);
        float xk = num * rcp_ap(den);
        if (o == k) z = xk;
        rhs -= a[k] * xk;
    }

    // cof_n = M[n][0] * det * z_n   (lane index o == n here)
    float c0 = sm[SM_M + m*272 + o];      // Msh[m][0][n]
    out[((size_t)(b0 + m)*2 + s)*16 + o] = c0 * det * z;
}

extern "C" void kernel_launch(void* const* d_in, const int* in_sizes, int n_in,
                              void* d_out, int out_size)
{
    const float* eq  = (const float*)d_in[0];
    const float* rei = (const float*)d_in[1];
    const float* W   = (const float*)d_in[2];
    const float* b   = (const float*)d_in[3];
    const float* ed  = (const float*)d_in[4];
    const float* ei  = (const float*)d_in[5];
    float* out = (float*)d_out;

    int B = in_sizes[0] / (32 * 256);        // 4096
    dim3 grid((B / 8) * 2);                  // 8 batches x 1 spin per block
    ocae2<<<grid, THREADS>>>(eq, rei, W, b, ed, ei, out);
}

// round 5
// speedup vs baseline: 3.3259x; 1.2360x over previous
#include <cuda_runtime.h>

#define THREADS 128

// ---------- packed f32x2 helpers ----------
__device__ __forceinline__ unsigned long long pk2(float lo, float hi) {
    unsigned long long r;
    asm("mov.b64 %0, {%1, %2};" : "=l"(r) : "f"(lo), "f"(hi));
    return r;
}
__device__ __forceinline__ void upk2(unsigned long long v, float& lo, float& hi) {
    asm("mov.b64 {%0, %1}, %2;" : "=f"(lo), "=f"(hi) : "l"(v));
}
__device__ __forceinline__ void ffma2(unsigned long long& acc, unsigned long long a, unsigned long long b) {
    asm("fma.rn.f32x2 %0, %1, %2, %0;" : "+l"(acc) : "l"(a), "l"(b));
}
__device__ __forceinline__ unsigned long long mul2(unsigned long long a, unsigned long long b) {
    unsigned long long r; asm("mul.rn.f32x2 %0, %1, %2;" : "=l"(r) : "l"(a), "l"(b)); return r;
}
__device__ __forceinline__ float sqrt_ap(float x){ float r; asm("sqrt.approx.f32 %0, %1;" : "=f"(r) : "f"(x)); return r; }
__device__ __forceinline__ float rcp_ap (float x){ float r; asm("rcp.approx.f32 %0, %1;"  : "=f"(r) : "f"(x)); return r; }

// smem (floats):
//  W   [256][16]            4096
//  S   [8][8][12]           768    (A^T A quadratic forms, o-pair interleaved)
//  EI  [8][16]              128
//  M   [8][16*17]           2176   (M^T rows, stride 17)
//  X   union{ xtile[128][36], rei[128][28] }  4608
#define SM_W  0
#define SM_S  4096
#define SM_EI (4096 + 768)
#define SM_M  (4096 + 768 + 128)
#define SM_X  (4096 + 768 + 128 + 2176)
#define SMEM_FLOATS (SM_X + 128*36)

__global__ __launch_bounds__(THREADS, 4)
void ocae3(const float* __restrict__ eq,  const float* __restrict__ rei,
           const float* __restrict__ Wg,  const float* __restrict__ bias,
           const float* __restrict__ envdim, const float* __restrict__ envion,
           float* __restrict__ out)
{
    __shared__ float sm[SMEM_FLOATS];
    const int tid = threadIdx.x;
    const int s   = blockIdx.x & 1;          // spin
    const int b0  = (blockIdx.x >> 1) * 8;   // 8 batches per block

    // ---------------- stage constants ----------------
    {
        const float4* Wsrc = (const float4*)(Wg + (size_t)s * 4096);
        #pragma unroll
        for (int i = tid; i < 1024; i += THREADS)
            *(float4*)(sm + SM_W + i*4) = __ldg(Wsrc + i);

        sm[SM_EI + tid] = envion[s*128 + tid];

        // S = A^T A per (i,o), o-pair-interleaved sextets of f32x2
        int ii = tid >> 4, oo = tid & 15;
        const float* A = envdim + s*1152 + ii*144 + oo*9;
        float a00=A[0],a01=A[1],a02=A[2], a10=A[3],a11=A[4],a12=A[5], a20=A[6],a21=A[7],a22=A[8];
        float s00 = a00*a00 + a10*a10 + a20*a20;
        float s11 = a01*a01 + a11*a11 + a21*a21;
        float s22 = a02*a02 + a12*a12 + a22*a22;
        float s01 = 2.f*(a00*a01 + a10*a11 + a20*a21);
        float s02 = 2.f*(a00*a02 + a10*a12 + a20*a22);
        float s12 = 2.f*(a01*a02 + a11*a12 + a21*a22);
        float* dst = sm + SM_S + (ii*8 + (oo>>1))*12 + (oo&1);
        dst[0]=s00; dst[2]=s11; dst[4]=s22; dst[6]=s01; dst[8]=s02; dst[10]=s12;
    }

    // ---------------- GEMM: 1 row x 16 orbitals per thread ----------------
    const int m = tid >> 4;          // local matrix 0..7
    const int n = tid & 15;          // row in matrix

    unsigned long long acc[8];
    {
        const float4* bp = (const float4*)(bias + s*16);
        float4 b0v = __ldg(bp), b1v = __ldg(bp+1), b2v = __ldg(bp+2), b3v = __ldg(bp+3);
        acc[0]=pk2(b0v.x,b0v.y); acc[1]=pk2(b0v.z,b0v.w);
        acc[2]=pk2(b1v.x,b1v.y); acc[3]=pk2(b1v.z,b1v.w);
        acc[4]=pk2(b2v.x,b2v.y); acc[5]=pk2(b2v.z,b2v.w);
        acc[6]=pk2(b3v.x,b3v.y); acc[7]=pk2(b3v.z,b3v.w);
    }

    // coalesced staging pointers: thread loads float4 f = tid + 128k of each chunk
    const float4* gptr[8];
    int soff[8];
    #pragma unroll
    for (int k = 0; k < 8; k++) {
        int rf = (tid >> 3) + 16*k;                         // source row 0..127
        size_t grow = ((size_t)(b0 + (rf>>4)))*32 + s*16 + (rf&15);
        gptr[k] = (const float4*)(eq + grow*256) + (tid & 7);
        soff[k] = rf*36 + (tid & 7)*4;
    }

    float4 pre[8];
    #pragma unroll
    for (int k = 0; k < 8; k++) pre[k] = __ldg(gptr[k]);    // chunk 0 (prefetch before const-sync barrier)

    __syncthreads();   // constants staged; also gates first xtile write below

    for (int c = 0; c < 8; c++) {
        #pragma unroll
        for (int k = 0; k < 8; k++)
            *(float4*)(sm + SM_X + soff[k]) = pre[k];
        __syncthreads();                                    // xtile chunk c ready

        if (c < 7) {
            #pragma unroll
            for (int k = 0; k < 8; k++) pre[k] = __ldg(gptr[k] + (c+1)*8);
        }

        const float* xr = sm + SM_X + tid*36;
        #pragma unroll
        for (int q = 0; q < 8; q++) {
            float4 x4 = *(const float4*)(xr + q*4);
            float xa[4]; *(float4*)xa = x4;
            #pragma unroll
            for (int e = 0; e < 4; e++) {
                const ulonglong2* wp = (const ulonglong2*)(sm + SM_W + (c*32 + q*4 + e)*16);
                ulonglong2 wA = wp[0], wB = wp[1], wC = wp[2], wD = wp[3];
                unsigned long long xx = pk2(xa[e], xa[e]);
                ffma2(acc[0], xx, wA.x); ffma2(acc[1], xx, wA.y);
                ffma2(acc[2], xx, wB.x); ffma2(acc[3], xx, wB.y);
                ffma2(acc[4], xx, wC.x); ffma2(acc[5], xx, wC.y);
                ffma2(acc[6], xx, wD.x); ffma2(acc[7], xx, wD.y);
            }
        }
        __syncthreads();                                    // chunk c consumed; xtile reusable
    }

    // ---------------- stage rei coalesced into X region ----------------
    #pragma unroll
    for (int k = 0; k < 6; k++) {
        int f  = tid + 128*k;       // 0..767
        int rf = f / 6;
        int qf = f - rf*6;
        size_t grow = ((size_t)(b0 + (rf>>4)))*32 + s*16 + (rf&15);
        float4 v = __ldg((const float4*)(rei) + grow*6 + qf);
        *(float4*)(sm + SM_X + rf*28 + qf*4) = v;
    }
    __syncthreads();

    // ---------------- env + M ----------------
    {
        const float* rv = sm + SM_X + tid*28;
        unsigned long long ev[8] = {0,0,0,0,0,0,0,0};
        #pragma unroll
        for (int i = 0; i < 8; i++) {
            float r0 = rv[i*3], r1 = rv[i*3+1], r2 = rv[i*3+2];
            unsigned long long p00 = pk2(r0*r0, r0*r0);
            unsigned long long p11 = pk2(r1*r1, r1*r1);
            unsigned long long p22 = pk2(r2*r2, r2*r2);
            unsigned long long p01 = pk2(r0*r1, r0*r1);
            unsigned long long p02 = pk2(r0*r2, r0*r2);
            unsigned long long p12 = pk2(r1*r2, r1*r2);
            const float* Sb = sm + SM_S + i*96;
            const unsigned long long* Eb = (const unsigned long long*)(sm + SM_EI) + i*8;
            #pragma unroll
            for (int op = 0; op < 8; op++) {
                const ulonglong2* Sp = (const ulonglong2*)(Sb + op*12);
                ulonglong2 sA = Sp[0], sB = Sp[1], sC = Sp[2];
                unsigned long long q = 0ull;
                ffma2(q, sA.x, p00); ffma2(q, sA.y, p11); ffma2(q, sB.x, p22);
                ffma2(q, sB.y, p01); ffma2(q, sC.x, p02); ffma2(q, sC.y, p12);
                float q0, q1; upk2(q, q0, q1);
                float e0 = __expf(-sqrt_ap(fmaxf(q0, 0.f)));
                float e1 = __expf(-sqrt_ap(fmaxf(q1, 0.f)));
                ffma2(ev[op], pk2(e0, e1), Eb[op]);
            }
        }
        // M[n][o] -> Msh[m][o][n] (stride 17)
        float* Mb = sm + SM_M + m*272 + n;
        #pragma unroll
        for (int op = 0; op < 8; op++) {
            unsigned long long mm = mul2(acc[op], ev[op]);
            float m0, m1; upk2(mm, m0, m1);
            Mb[(2*op)*17] = m0; Mb[(2*op+1)*17] = m1;
        }
    }
    __syncthreads();

    // ---------------- cofactors: register LU, 2 matrices per warp ----------------
    const unsigned FULL = 0xffffffffu;
    const int lane = tid & 31;
    const int w    = tid >> 5;
    const int seg  = lane >> 4;
    const int o    = lane & 15;          // row of A = M^T
    const int mm   = w + seg*4;

    float a[17];
    {
        const float* Ma = sm + SM_M + mm*272 + o*17;
        #pragma unroll
        for (int j = 0; j < 16; j++) a[j] = Ma[j];
        a[16] = (o == 0) ? 1.f : 0.f;    // rhs e0
    }
    float det = 1.f;

    #pragma unroll
    for (int k = 0; k < 16; k++) {
        float v = (o >= k) ? fabsf(a[k]) : -1.f;
        int   p = o;
        #pragma unroll
        for (int off = 8; off; off >>= 1) {
            float ov = __shfl_xor_sync(FULL, v, off, 16);
            int   oq = __shfl_xor_sync(FULL, p, off, 16);
            if (ov > v || (ov == v && oq < p)) { v = ov; p = oq; }
        }
        float pvk = __shfl_sync(FULL, a[k], p, 16);
        float kvk = __shfl_sync(FULL, a[k], k, 16);
        if (o == k) a[k] = pvk; else if (o == p) a[k] = kvk;
        det = (p != k) ? -det : det;
        det *= pvk;
        float mlt = (o > k) ? a[k] * rcp_ap(pvk) : 0.f;
        #pragma unroll
        for (int j = k + 1; j < 17; j++) {
            float pv = __shfl_sync(FULL, a[j], p, 16);
            float kv = __shfl_sync(FULL, a[j], k, 16);
            if (o == k) a[j] = pv; else if (o == p) a[j] = kv;
            a[j] -= mlt * pv;
        }
    }

    // back-substitution: U z = rhs
    float z = 0.f;
    float rhs = a[16];
    #pragma unroll
    for (int k = 15; k >= 0; k--) {
        float num = __shfl_sync(FULL, rhs,  k, 16);
        float den = __shfl_sync(FULL, a[k], k, 16);
        float xk = num * rcp_ap(den);
        if (o == k) z = xk;
        rhs -= a[k] * xk;
    }

    // cof_n = M[n][0] * det * z_n
    float c0 = sm[SM_M + mm*272 + o];
    out[((size_t)(b0 + mm)*2 + s)*16 + o] = c0 * det * z;
}

extern "C" void kernel_launch(void* const* d_in, const int* in_sizes, int n_in,
                              void* d_out, int out_size)
{
    const float* eq  = (const float*)d_in[0];
    const float* rei = (const float*)d_in[1];
    const float* W   = (const float*)d_in[2];
    const float* b   = (const float*)d_in[3];
    const float* ed  = (const float*)d_in[4];
    const float* ei  = (const float*)d_in[5];
    float* out = (float*)d_out;

    int B = in_sizes[0] / (32 * 256);        // 4096
    dim3 grid((B / 8) * 2);
    ocae3<<<grid, THREADS>>>(eq, rei, W, b, ed, ei, out);
}